// round 12
// baseline (speedup 1.0000x reference)
#include <cuda_runtime.h>
#include <cstdint>

#define H  128
#define NH 8
#define NQ 2304

__device__ float g_WT[12 * H * H];
__device__ float g_u [NQ * 1024];
__device__ float g_w [NQ * 1024];
__device__ float g_vb[NQ * 1024];   // [q>>3][n*128+i][q&7]
__device__ float g_rb[NQ * 1024];
__device__ float g_buf0[NQ * H];
__device__ float g_buf1[NQ * H];

__global__ void transpose_k(const float* p0, const float* p1, const float* p2,
                            const float* p3, const float* p4, const float* p5)
{
    const float* ps[6] = {p0, p1, p2, p3, p4, p5};
    int slot = blockIdx.x >> 2;                  // 0..11
    int part = blockIdx.x & 3;
    const float* Wm = ps[slot >> 1] + (slot & 1) * H * H;
    float* O = g_WT + slot * H * H;
    int t = threadIdx.x;
    for (int c = part * 32; c < part * 32 + 32; ++c)
        O[c * H + t] = Wm[t * H + c];
}

__device__ __forceinline__ void cp16(uint32_t dst, const float* src) {
    asm volatile("cp.async.cg.shared.global [%0], [%1], 16;" :: "r"(dst), "l"(src));
}

// ---------------- Kernel A (first stage only): qh = x@Wq; u/w ----------------
// block = 4 queries, 256 threads.
__global__ __launch_bounds__(256) void stage_uw(
    const float* __restrict__ xin,
    const float* __restrict__ Wq,
    const float* __restrict__ WkT, const float* __restrict__ WrkT,
    float* __restrict__ gu, float* __restrict__ gw)
{
    __shared__ float sx [4][128];
    __shared__ float sqh[4][128];
    const int tid = threadIdx.x;
    const int t = tid & 127, g = tid >> 7;
    const int q0 = blockIdx.x * 4;

    for (int e = tid; e < 512; e += 256)
        sx[e >> 7][e & 127] = xin[q0 * H + e];
    __syncthreads();

    {
        float a0 = 0.f, a1 = 0.f;
        const float* x0 = sx[2 * g];
        const float* x1 = sx[2 * g + 1];
        #pragma unroll 8
        for (int i = 0; i < H; ++i) {
            float wv = Wq[i * H + t];
            a0 += x0[i] * wv; a1 += x1[i] * wv;
        }
        sqh[2 * g    ][t] = a0;
        sqh[2 * g + 1][t] = a1;
    }
    __syncthreads();

    #pragma unroll 1
    for (int nn = 0; nn < 4; ++nn) {
        int n = 4 * g + nn;
        float wk[16], wr[16];
        #pragma unroll
        for (int d = 0; d < 16; ++d) {
            wk[d] = WkT [(n * 16 + d) * H + t];
            wr[d] = WrkT[(n * 16 + d) * H + t];
        }
        float uo[4], wo4[4];
        #pragma unroll
        for (int q = 0; q < 4; ++q) { uo[q] = 0.f; wo4[q] = 0.f; }
        #pragma unroll
        for (int d = 0; d < 16; ++d) {
            #pragma unroll
            for (int q = 0; q < 4; ++q) {
                float qv = sqh[q][n * 16 + d];
                uo[q]  += qv * wk[d];
                wo4[q] += qv * wr[d];
            }
        }
        #pragma unroll
        for (int q = 0; q < 4; ++q) {
            gu[(q0 + q) * 1024 + n * H + t] = uo[q];
            gw[(q0 + q) * 1024 + n * H + t] = wo4[q];
        }
    }
}

// ---------------- Kernel B: weight-free attention core -----------------------
__global__ __launch_bounds__(128) void attn_core(
    const float* __restrict__ gu, const float* __restrict__ gw,
    const float* __restrict__ ksrc, const float* __restrict__ rpesrc,
    const int* __restrict__ knn, const unsigned char* __restrict__ mask,
    float* __restrict__ gvb, float* __restrict__ grb,
    int stage, int S, int B)
{
    extern __shared__ float sm[];
    float* sm_u   = sm;                // 1024 [n*128+i]
    float* sm_w   = sm + 1024;         // 1024
    float* sm_scp = sm + 2048;         // P*512 partials; slot p=0 holds probs
    const int P = 128 >> B;
    float* sm_k   = sm_scp + P * 512;  // S*132
    float* sm_r   = sm_k + S * 132;

    __shared__ int kbase[64], rbase[64], mflag[64];

    const int q = blockIdx.x;
    const int t = threadIdx.x;

    if (t < S) {
        int kb, rb, mf;
        if (stage == 1) {
            kb = (q * S + t) * H; rb = kb;
            mf = mask[q * S + t];
        } else if (stage == 2) {
            int idx = knn[q * 32 + t];
            kb = (q * 128 + idx) * H; rb = kb;
            mf = mask[q * 128 + idx];
        } else {
            int g = q / 48, qn = q % 48;
            int idx = knn[(g * 48 + qn) * 16 + t];
            kb = ((g * 48 + idx) * 50 + 49) * H;
            rb = ((g * 48 + qn) * 48 + idx) * H;
            mf = mask[(g * 48 + qn) * 48 + idx];
        }
        kbase[t] = kb; rbase[t] = rb; mflag[t] = mf;
    }
    __syncthreads();

    {
        uint32_t su  = (uint32_t)__cvta_generic_to_shared(sm_u);
        uint32_t sw  = (uint32_t)__cvta_generic_to_shared(sm_w);
        for (int c = t; c < 256; c += 128) {
            cp16(su + c * 16, gu + q * 1024 + c * 4);
            cp16(sw + c * 16, gw + q * 1024 + c * 4);
        }
        uint32_t smk = (uint32_t)__cvta_generic_to_shared(sm_k);
        uint32_t smr = (uint32_t)__cvta_generic_to_shared(sm_r);
        for (int c = t; c < S * 32; c += 128) {
            int s = c >> 5, j = c & 31;
            cp16(smk + s * 528 + j * 16, ksrc   + kbase[s] + j * 4);
            cp16(smr + s * 528 + j * 16, rpesrc + rbase[s] + j * 4);
        }
        asm volatile("cp.async.commit_group;");
        asm volatile("cp.async.wait_group 0;");
    }
    __syncthreads();

    // scores: thread = (part p, key s); part p covers i in [p<<B,(p+1)<<B).
    {
        int p = t >> B, s = t & ((1 << B) - 1);
        if (s < S) {
            int i0 = p << B;
            const int C = 1 << B;
            const float* kk = &sm_k[s * 132 + i0];
            const float* rr = &sm_r[s * 132 + i0];
            float acc[NH];
            #pragma unroll
            for (int n = 0; n < NH; ++n) acc[n] = 0.f;
            #pragma unroll 4
            for (int ii = 0; ii < C; ii += 4) {
                float4 k4 = *(const float4*)(kk + ii);
                float4 r4 = *(const float4*)(rr + ii);
                #pragma unroll
                for (int n = 0; n < NH; ++n) {
                    float4 u4 = *(const float4*)(sm_u + n * 128 + i0 + ii);
                    float4 w4 = *(const float4*)(sm_w + n * 128 + i0 + ii);
                    acc[n] += k4.x * u4.x + k4.y * u4.y + k4.z * u4.z + k4.w * u4.w
                            + r4.x * w4.x + r4.y * w4.y + r4.z * w4.z + r4.w * w4.w;
                }
            }
            #pragma unroll
            for (int n = 0; n < NH; ++n) sm_scp[p * 512 + s * NH + n] = acc[n];
        }
    }
    __syncthreads();

    // softmax: 128 threads, 16 lanes per head.
    {
        int n = t >> 4, j = t & 15;
        float mx = -1e30f;
        for (int s = j; s < S; s += 16) {
            float v = 0.f;
            for (int p = 0; p < P; ++p) v += sm_scp[p * 512 + s * NH + n];
            v *= 0.25f;
            if (mflag[s]) v = -1e9f;
            sm_scp[s * NH + n] = v;
            mx = fmaxf(mx, v);
        }
        #pragma unroll
        for (int o = 8; o; o >>= 1) mx = fmaxf(mx, __shfl_xor_sync(0xffffffffu, mx, o));
        float sum = 0.f;
        for (int s = j; s < S; s += 16) {
            float pe = __expf(sm_scp[s * NH + n] - mx);
            sm_scp[s * NH + n] = pe; sum += pe;
        }
        #pragma unroll
        for (int o = 8; o; o >>= 1) sum += __shfl_xor_sync(0xffffffffu, sum, o);
        float inv = 1.f / sum;
        for (int s = j; s < S; s += 16) sm_scp[s * NH + n] *= inv;
    }
    __syncthreads();

    {
        float vb[NH], rb2[NH];
        #pragma unroll
        for (int n = 0; n < NH; ++n) { vb[n] = 0.f; rb2[n] = 0.f; }
        for (int s = 0; s < S; ++s) {
            float kv = sm_k[s * 132 + t];
            float rv = sm_r[s * 132 + t];
            float4 p0 = *(const float4*)&sm_scp[s * NH];
            float4 p1 = *(const float4*)&sm_scp[s * NH + 4];
            vb[0] += p0.x * kv;  rb2[0] += p0.x * rv;
            vb[1] += p0.y * kv;  rb2[1] += p0.y * rv;
            vb[2] += p0.z * kv;  rb2[2] += p0.z * rv;
            vb[3] += p0.w * kv;  rb2[3] += p0.w * rv;
            vb[4] += p1.x * kv;  rb2[4] += p1.x * rv;
            vb[5] += p1.y * kv;  rb2[5] += p1.y * rv;
            vb[6] += p1.z * kv;  rb2[6] += p1.z * rv;
            vb[7] += p1.w * kv;  rb2[7] += p1.w * rv;
        }
        // q-interleaved (width 8): [(q>>3)*8192 + (n*128+t)*8 + (q&7)]
        int base = (q & ~7) * 1024 + (q & 7);
        #pragma unroll
        for (int n = 0; n < NH; ++n) {
            gvb[base + (n * 128 + t) * 8] = vb[n];
            grb[base + (n * 128 + t) * 8] = rb2[n];
        }
    }
}

// ---------------- Kernel C+A': out_proj fused with next-stage uw -------------
// block = 8 queries, 512 threads (4 groups), grid 288.
__global__ __launch_bounds__(512) void out_proj_uw(
    const float* __restrict__ xin,
    const float* __restrict__ gvb, const float* __restrict__ grb,
    const float* __restrict__ Wv, const float* __restrict__ Wrv,
    const float* __restrict__ Wo,
    float* __restrict__ xout,
    const float* __restrict__ Wq2,
    const float* __restrict__ WkT2, const float* __restrict__ WrkT2,
    float* __restrict__ gu, float* __restrict__ gw, int do_next)
{
    extern __shared__ __align__(16) float smc[];
    float* svb8 = smc;                 // 8192  [(n*128+i)*8 + q]
    float* srb8 = smc + 8192;          // 8192
    float* sof8 = smc + 16384;         // 1024  [i*8 + q]
    float* sxo8 = smc + 17408;         // 1024  [q*128 + t]
    float* part = smc + 18432;         // 4096  [g*1024 + q*128 + t]

    const int tid = threadIdx.x;
    const int t = tid & 127, g = tid >> 7;     // g in 0..3
    const int q0 = blockIdx.x * 8;
    const int n = t >> 4;
    const int i0 = g * 32;

    // Stage vb/rb (contiguous: q0*1024 == (q0/8)*8192).
    {
        uint32_t a = (uint32_t)__cvta_generic_to_shared(svb8);
        uint32_t b = (uint32_t)__cvta_generic_to_shared(srb8);
        for (int c = tid; c < 2048; c += 512) {
            cp16(a + c * 16, gvb + q0 * 1024 + c * 4);
            cp16(b + c * 16, grb + q0 * 1024 + c * 4);
        }
        asm volatile("cp.async.commit_group;");
        asm volatile("cp.async.wait_group 0;");
    }
    __syncthreads();

    // Phase 1: of[q][t] = vb[q][n]·Wv[:,t] + rb[q][n]·Wrv[:,t]   (i in [i0,i0+32))
    {
        float acc[8];
        #pragma unroll
        for (int q = 0; q < 8; ++q) acc[q] = 0.f;
        #pragma unroll 4
        for (int ii = 0; ii < 32; ++ii) {
            int i = i0 + ii;
            float wv = Wv [i * H + t];
            float wr = Wrv[i * H + t];
            const float* vbp = &svb8[(n * 128 + i) * 8];
            const float* rbp = &srb8[(n * 128 + i) * 8];
            float4 vlo = *(const float4*)(vbp);
            float4 vhi = *(const float4*)(vbp + 4);
            float4 rlo = *(const float4*)(rbp);
            float4 rhi = *(const float4*)(rbp + 4);
            acc[0] += vlo.x * wv + rlo.x * wr;
            acc[1] += vlo.y * wv + rlo.y * wr;
            acc[2] += vlo.z * wv + rlo.z * wr;
            acc[3] += vlo.w * wv + rlo.w * wr;
            acc[4] += vhi.x * wv + rhi.x * wr;
            acc[5] += vhi.y * wv + rhi.y * wr;
            acc[6] += vhi.z * wv + rhi.z * wr;
            acc[7] += vhi.w * wv + rhi.w * wr;
        }
        #pragma unroll
        for (int q = 0; q < 8; ++q) part[g * 1024 + q * 128 + t] = acc[q];
    }
    __syncthreads();
    if (g == 0) {
        float4 lo, hi;
        lo.x = part[0*128+t] + part[1024+0*128+t] + part[2048+0*128+t] + part[3072+0*128+t];
        lo.y = part[1*128+t] + part[1024+1*128+t] + part[2048+1*128+t] + part[3072+1*128+t];
        lo.z = part[2*128+t] + part[1024+2*128+t] + part[2048+2*128+t] + part[3072+2*128+t];
        lo.w = part[3*128+t] + part[1024+3*128+t] + part[2048+3*128+t] + part[3072+3*128+t];
        hi.x = part[4*128+t] + part[1024+4*128+t] + part[2048+4*128+t] + part[3072+4*128+t];
        hi.y = part[5*128+t] + part[1024+5*128+t] + part[2048+5*128+t] + part[3072+5*128+t];
        hi.z = part[6*128+t] + part[1024+6*128+t] + part[2048+6*128+t] + part[3072+6*128+t];
        hi.w = part[7*128+t] + part[1024+7*128+t] + part[2048+7*128+t] + part[3072+7*128+t];
        *(float4*)&sof8[t * 8]     = lo;
        *(float4*)&sof8[t * 8 + 4] = hi;
    }
    __syncthreads();

    // Phase 2: x_out = x + of @ Wo   (i in [i0,i0+32))
    {
        float acc[8];
        #pragma unroll
        for (int q = 0; q < 8; ++q) acc[q] = 0.f;
        #pragma unroll 4
        for (int ii = 0; ii < 32; ++ii) {
            int i = i0 + ii;
            float wo = Wo[i * H + t];
            float4 flo = *(const float4*)&sof8[i * 8];
            float4 fhi = *(const float4*)&sof8[i * 8 + 4];
            acc[0] += flo.x * wo;  acc[1] += flo.y * wo;
            acc[2] += flo.z * wo;  acc[3] += flo.w * wo;
            acc[4] += fhi.x * wo;  acc[5] += fhi.y * wo;
            acc[6] += fhi.z * wo;  acc[7] += fhi.w * wo;
        }
        #pragma unroll
        for (int q = 0; q < 8; ++q) part[g * 1024 + q * 128 + t] = acc[q];
    }
    __syncthreads();
    // Combine + residual + write: split 8 queries across 4 groups (2 each).
    {
        #pragma unroll
        for (int qq = 0; qq < 2; ++qq) {
            int q = 2 * g + qq;
            float v = xin[(q0 + q) * H + t]
                    + part[q * 128 + t] + part[1024 + q * 128 + t]
                    + part[2048 + q * 128 + t] + part[3072 + q * 128 + t];
            sxo8[q * 128 + t] = v;
            xout[(q0 + q) * H + t] = v;
        }
    }
    __syncthreads();

    if (!do_next) return;

    // Phase 3: next-stage qh = x_out @ Wq2  (group g does queries 2g, 2g+1)
    {
        float a0 = 0.f, a1 = 0.f;
        const float* x0 = &sxo8[(2 * g    ) * 128];
        const float* x1 = &sxo8[(2 * g + 1) * 128];
        #pragma unroll 8
        for (int i = 0; i < H; ++i) {
            float wv = Wq2[i * H + t];
            a0 += x0[i] * wv; a1 += x1[i] * wv;
        }
        part[(2 * g    ) * 128 + t] = a0;
        part[(2 * g + 1) * 128 + t] = a1;
    }
    __syncthreads();

    // Phase 4: u/w; group g handles heads 2g, 2g+1 for all 8 queries.
    #pragma unroll 1
    for (int nn = 0; nn < 2; ++nn) {
        int hn = 2 * g + nn;
        float wk[16], wr[16];
        #pragma unroll
        for (int d = 0; d < 16; ++d) {
            wk[d] = WkT2 [(hn * 16 + d) * H + t];
            wr[d] = WrkT2[(hn * 16 + d) * H + t];
        }
        float uo[8], wo8[8];
        #pragma unroll
        for (int q = 0; q < 8; ++q) { uo[q] = 0.f; wo8[q] = 0.f; }
        #pragma unroll
        for (int d = 0; d < 16; ++d) {
            #pragma unroll
            for (int q = 0; q < 8; ++q) {
                float qv = part[q * 128 + hn * 16 + d];
                uo[q]  += qv * wk[d];
                wo8[q] += qv * wr[d];
            }
        }
        #pragma unroll
        for (int q = 0; q < 8; ++q) {
            gu[(q0 + q) * 1024 + hn * H + t] = uo[q];
            gw[(q0 + q) * 1024 + hn * H + t] = wo8[q];
        }
    }
}

extern "C" void kernel_launch(void* const* d_in, const int* in_sizes, int n_in,
                              void* d_out, int out_size)
{
    bool sig = (in_sizes[6] == 32768);

    const float* x_m    = (const float*)d_in[0];
    const float* x_a    = (const float*)d_in[1];
    const float* x_pl   = (const float*)d_in[2];
    const float* rpe_t  = (const float*)d_in[3];
    const float* rpe_pl = (const float*)d_in[4];
    const float* rpe_a  = (const float*)d_in[5];

    const float* W[3][6];
    int wb = sig ? 6 : 11;
    for (int s = 0; s < 3; ++s)
        for (int j = 0; j < 6; ++j)
            W[s][j] = (const float*)d_in[wb + s * 6 + j];

    int kb = sig ? 24 : 6;
    const int* knn_pl = (const int*)d_in[kb + 0];
    const int* knn_a  = (const int*)d_in[kb + 1];
    const unsigned char* mk_t  = (const unsigned char*)d_in[kb + 2];
    const unsigned char* mk_pl = (const unsigned char*)d_in[kb + 3];
    const unsigned char* mk_a  = (const unsigned char*)d_in[kb + 4];

    cudaFuncSetAttribute(attn_core, cudaFuncAttributeMaxDynamicSharedMemorySize, 65088);
    cudaFuncSetAttribute(out_proj_uw, cudaFuncAttributeMaxDynamicSharedMemorySize, 92160);

    float *buf0, *buf1, *wt, *gu, *gw, *gvb, *grb;
    cudaGetSymbolAddress((void**)&buf0, g_buf0);
    cudaGetSymbolAddress((void**)&buf1, g_buf1);
    cudaGetSymbolAddress((void**)&wt,   g_WT);
    cudaGetSymbolAddress((void**)&gu,   g_u);
    cudaGetSymbolAddress((void**)&gw,   g_w);
    cudaGetSymbolAddress((void**)&gvb,  g_vb);
    cudaGetSymbolAddress((void**)&grb,  g_rb);

    transpose_k<<<48, 128>>>(W[0][1], W[0][3], W[1][1], W[1][3], W[2][1], W[2][3]);

    const int Ss[3] = {50, 32, 16};
    const int Bs[3] = {6, 5, 4};
    const float* cur = x_m;
    float* bufs[2] = {buf0, buf1};
    int bi = 0;

    // First-stage u/w.
    stage_uw<<<NQ / 4, 256>>>(x_m, W[0][0],
                              wt + ((0 * 2 + 0) * 2 + 0) * H * H,
                              wt + ((0 * 2 + 1) * 2 + 0) * H * H, gu, gw);

    for (int idx = 0; idx < 6; ++idx) {
        int l = idx / 3, s = idx % 3;
        int l2 = (idx + 1) / 3, s2 = (idx + 1) % 3;
        float* outp = (idx == 5) ? (float*)d_out : bufs[bi];
        int S = Ss[s], B = Bs[s];
        const float* ksrc = (s == 1) ? x_pl : x_a;
        const float* rp   = (s == 0) ? rpe_t : (s == 1) ? rpe_pl : rpe_a;
        const int*   kn   = (s == 1) ? knn_pl : (s == 2) ? knn_a : (const int*)0;
        const unsigned char* mk = (s == 0) ? mk_t : (s == 1) ? mk_pl : mk_a;

        const float* Wv  = W[s][2] + l * H * H;
        const float* Wrv = W[s][4] + l * H * H;
        const float* Wo  = W[s][5] + l * H * H;

        int P = 128 >> B;
        size_t smemB = (size_t)(2048 + P * 512 + S * 264) * sizeof(float);
        attn_core<<<NQ, 128, smemB>>>(gu, gw, ksrc, rp, kn, mk,
                                      gvb, grb, s + 1, S, B);

        int do_next = (idx < 5);
        const float* Wq2   = do_next ? W[s2][0] + l2 * H * H : Wv;
        const float* WkT2  = do_next ? wt + ((s2 * 2 + 0) * 2 + l2) * H * H : Wv;
        const float* WrkT2 = do_next ? wt + ((s2 * 2 + 1) * 2 + l2) * H * H : Wv;

        out_proj_uw<<<NQ / 8, 512, 90112>>>(cur, gvb, grb, Wv, Wrv, Wo, outp,
                                            Wq2, WkT2, WrkT2, gu, gw, do_next);
        cur = outp;
        bi ^= 1;
    }
}

// round 13
// speedup vs baseline: 1.1088x; 1.1088x over previous
#include <cuda_runtime.h>
#include <cstdint>

#define H  128
#define NH 8
#define NQ 2304

__device__ float g_WT[12 * H * H];
__device__ float g_u [NQ * 1024];
__device__ float g_w [NQ * 1024];
__device__ float g_vb[NQ * 1024];   // [q>>2][n*128+i][q&3]  (width-4 interleave)
__device__ float g_rb[NQ * 1024];
__device__ float g_buf0[NQ * H];
__device__ float g_buf1[NQ * H];

__global__ void transpose_k(const float* p0, const float* p1, const float* p2,
                            const float* p3, const float* p4, const float* p5)
{
    const float* ps[6] = {p0, p1, p2, p3, p4, p5};
    int slot = blockIdx.x >> 2;                  // 0..11
    int part = blockIdx.x & 3;
    const float* Wm = ps[slot >> 1] + (slot & 1) * H * H;
    float* O = g_WT + slot * H * H;
    int t = threadIdx.x;
    for (int c = part * 32; c < part * 32 + 32; ++c)
        O[c * H + t] = Wm[t * H + c];
}

__device__ __forceinline__ void cp16(uint32_t dst, const float* src) {
    asm volatile("cp.async.cg.shared.global [%0], [%1], 16;" :: "r"(dst), "l"(src));
}

// ---------------- Kernel A (first stage only): qh = x@Wq; u/w ----------------
__global__ __launch_bounds__(256) void stage_uw(
    const float* __restrict__ xin,
    const float* __restrict__ Wq,
    const float* __restrict__ WkT, const float* __restrict__ WrkT,
    float* __restrict__ gu, float* __restrict__ gw)
{
    __shared__ float sx [4][128];
    __shared__ float sqh[4][128];
    const int tid = threadIdx.x;
    const int t = tid & 127, g = tid >> 7;
    const int q0 = blockIdx.x * 4;

    for (int e = tid; e < 512; e += 256)
        sx[e >> 7][e & 127] = xin[q0 * H + e];
    __syncthreads();

    {
        float a0 = 0.f, a1 = 0.f;
        const float* x0 = sx[2 * g];
        const float* x1 = sx[2 * g + 1];
        #pragma unroll 8
        for (int i = 0; i < H; ++i) {
            float wv = Wq[i * H + t];
            a0 += x0[i] * wv; a1 += x1[i] * wv;
        }
        sqh[2 * g    ][t] = a0;
        sqh[2 * g + 1][t] = a1;
    }
    __syncthreads();

    #pragma unroll 1
    for (int nn = 0; nn < 4; ++nn) {
        int n = 4 * g + nn;
        float wk[16], wr[16];
        #pragma unroll
        for (int d = 0; d < 16; ++d) {
            wk[d] = WkT [(n * 16 + d) * H + t];
            wr[d] = WrkT[(n * 16 + d) * H + t];
        }
        float uo[4], wo4[4];
        #pragma unroll
        for (int q = 0; q < 4; ++q) { uo[q] = 0.f; wo4[q] = 0.f; }
        #pragma unroll
        for (int d = 0; d < 16; ++d) {
            #pragma unroll
            for (int q = 0; q < 4; ++q) {
                float qv = sqh[q][n * 16 + d];
                uo[q]  += qv * wk[d];
                wo4[q] += qv * wr[d];
            }
        }
        #pragma unroll
        for (int q = 0; q < 4; ++q) {
            gu[(q0 + q) * 1024 + n * H + t] = uo[q];
            gw[(q0 + q) * 1024 + n * H + t] = wo4[q];
        }
    }
}

// ---------------- Kernel B: weight-free attention core -----------------------
__global__ __launch_bounds__(128) void attn_core(
    const float* __restrict__ gu, const float* __restrict__ gw,
    const float* __restrict__ ksrc, const float* __restrict__ rpesrc,
    const int* __restrict__ knn, const unsigned char* __restrict__ mask,
    float* __restrict__ gvb, float* __restrict__ grb,
    int stage, int S, int B)
{
    extern __shared__ float sm[];
    float* sm_u   = sm;                // 1024 [n*128+i]
    float* sm_w   = sm + 1024;         // 1024
    float* sm_scp = sm + 2048;         // P*512 partials; slot p=0 holds probs
    const int P = 128 >> B;
    float* sm_k   = sm_scp + P * 512;  // S*132
    float* sm_r   = sm_k + S * 132;

    __shared__ int kbase[64], rbase[64], mflag[64];

    const int q = blockIdx.x;
    const int t = threadIdx.x;

    if (t < S) {
        int kb, rb, mf;
        if (stage == 1) {
            kb = (q * S + t) * H; rb = kb;
            mf = mask[q * S + t];
        } else if (stage == 2) {
            int idx = knn[q * 32 + t];
            kb = (q * 128 + idx) * H; rb = kb;
            mf = mask[q * 128 + idx];
        } else {
            int g = q / 48, qn = q % 48;
            int idx = knn[(g * 48 + qn) * 16 + t];
            kb = ((g * 48 + idx) * 50 + 49) * H;
            rb = ((g * 48 + qn) * 48 + idx) * H;
            mf = mask[(g * 48 + qn) * 48 + idx];
        }
        kbase[t] = kb; rbase[t] = rb; mflag[t] = mf;
    }
    __syncthreads();

    {
        uint32_t su  = (uint32_t)__cvta_generic_to_shared(sm_u);
        uint32_t sw  = (uint32_t)__cvta_generic_to_shared(sm_w);
        for (int c = t; c < 256; c += 128) {
            cp16(su + c * 16, gu + q * 1024 + c * 4);
            cp16(sw + c * 16, gw + q * 1024 + c * 4);
        }
        uint32_t smk = (uint32_t)__cvta_generic_to_shared(sm_k);
        uint32_t smr = (uint32_t)__cvta_generic_to_shared(sm_r);
        for (int c = t; c < S * 32; c += 128) {
            int s = c >> 5, j = c & 31;
            cp16(smk + s * 528 + j * 16, ksrc   + kbase[s] + j * 4);
            cp16(smr + s * 528 + j * 16, rpesrc + rbase[s] + j * 4);
        }
        asm volatile("cp.async.commit_group;");
        asm volatile("cp.async.wait_group 0;");
    }
    __syncthreads();

    // scores: thread = (part p, key s); part p covers i in [p<<B,(p+1)<<B).
    {
        int p = t >> B, s = t & ((1 << B) - 1);
        if (s < S) {
            int i0 = p << B;
            const int C = 1 << B;
            const float* kk = &sm_k[s * 132 + i0];
            const float* rr = &sm_r[s * 132 + i0];
            float acc[NH];
            #pragma unroll
            for (int n = 0; n < NH; ++n) acc[n] = 0.f;
            #pragma unroll 4
            for (int ii = 0; ii < C; ii += 4) {
                float4 k4 = *(const float4*)(kk + ii);
                float4 r4 = *(const float4*)(rr + ii);
                #pragma unroll
                for (int n = 0; n < NH; ++n) {
                    float4 u4 = *(const float4*)(sm_u + n * 128 + i0 + ii);
                    float4 w4 = *(const float4*)(sm_w + n * 128 + i0 + ii);
                    acc[n] += k4.x * u4.x + k4.y * u4.y + k4.z * u4.z + k4.w * u4.w
                            + r4.x * w4.x + r4.y * w4.y + r4.z * w4.z + r4.w * w4.w;
                }
            }
            #pragma unroll
            for (int n = 0; n < NH; ++n) sm_scp[p * 512 + s * NH + n] = acc[n];
        }
    }
    __syncthreads();

    // softmax: 128 threads, 16 lanes per head.
    {
        int n = t >> 4, j = t & 15;
        float mx = -1e30f;
        for (int s = j; s < S; s += 16) {
            float v = 0.f;
            for (int p = 0; p < P; ++p) v += sm_scp[p * 512 + s * NH + n];
            v *= 0.25f;
            if (mflag[s]) v = -1e9f;
            sm_scp[s * NH + n] = v;
            mx = fmaxf(mx, v);
        }
        #pragma unroll
        for (int o = 8; o; o >>= 1) mx = fmaxf(mx, __shfl_xor_sync(0xffffffffu, mx, o));
        float sum = 0.f;
        for (int s = j; s < S; s += 16) {
            float pe = __expf(sm_scp[s * NH + n] - mx);
            sm_scp[s * NH + n] = pe; sum += pe;
        }
        #pragma unroll
        for (int o = 8; o; o >>= 1) sum += __shfl_xor_sync(0xffffffffu, sum, o);
        float inv = 1.f / sum;
        for (int s = j; s < S; s += 16) sm_scp[s * NH + n] *= inv;
    }
    __syncthreads();

    {
        float vb[NH], rb2[NH];
        #pragma unroll
        for (int n = 0; n < NH; ++n) { vb[n] = 0.f; rb2[n] = 0.f; }
        for (int s = 0; s < S; ++s) {
            float kv = sm_k[s * 132 + t];
            float rv = sm_r[s * 132 + t];
            float4 p0 = *(const float4*)&sm_scp[s * NH];
            float4 p1 = *(const float4*)&sm_scp[s * NH + 4];
            vb[0] += p0.x * kv;  rb2[0] += p0.x * rv;
            vb[1] += p0.y * kv;  rb2[1] += p0.y * rv;
            vb[2] += p0.z * kv;  rb2[2] += p0.z * rv;
            vb[3] += p0.w * kv;  rb2[3] += p0.w * rv;
            vb[4] += p1.x * kv;  rb2[4] += p1.x * rv;
            vb[5] += p1.y * kv;  rb2[5] += p1.y * rv;
            vb[6] += p1.z * kv;  rb2[6] += p1.z * rv;
            vb[7] += p1.w * kv;  rb2[7] += p1.w * rv;
        }
        // width-4 interleave (R11-proven): [(q>>2)*4096 + (n*128+t)*4 + (q&3)]
        int base = (q & ~3) * 1024 + (q & 3);
        #pragma unroll
        for (int n = 0; n < NH; ++n) {
            gvb[base + (n * 128 + t) * 4] = vb[n];
            grb[base + (n * 128 + t) * 4] = rb2[n];
        }
    }
}

// ---------------- Kernel C+A': out_proj fused with next-stage uw -------------
// block = 8 queries (two width-4 groups), 512 threads, grid 288.
__global__ __launch_bounds__(512) void out_proj_uw(
    const float* __restrict__ xin,
    const float* __restrict__ gvb, const float* __restrict__ grb,
    const float* __restrict__ Wv, const float* __restrict__ Wrv,
    const float* __restrict__ Wo,
    float* __restrict__ xout,
    const float* __restrict__ Wq2,
    const float* __restrict__ WkT2, const float* __restrict__ WrkT2,
    float* __restrict__ gu, float* __restrict__ gw, int do_next)
{
    extern __shared__ __align__(16) float smc[];
    float* svb = smc;                  // 8192: [0,4096) q0..3, [4096,8192) q4..7
    float* srb = smc + 8192;           // 8192
    float* sof8 = smc + 16384;         // 1024  [i*8 + q]
    float* sxo8 = smc + 17408;         // 1024  [q*128 + t]
    float* part = smc + 18432;         // 4096  [g*1024 + q*128 + t]

    const int tid = threadIdx.x;
    const int t = tid & 127, g = tid >> 7;     // g in 0..3
    const int q0 = blockIdx.x * 8;
    const int n = t >> 4;
    const int i0 = g * 32;

    // Stage vb/rb: 8 queries = two consecutive width-4 groups, contiguous in gmem.
    {
        uint32_t a = (uint32_t)__cvta_generic_to_shared(svb);
        uint32_t b = (uint32_t)__cvta_generic_to_shared(srb);
        for (int c = tid; c < 2048; c += 512) {
            cp16(a + c * 16, gvb + q0 * 1024 + c * 4);
            cp16(b + c * 16, grb + q0 * 1024 + c * 4);
        }
        asm volatile("cp.async.commit_group;");
        asm volatile("cp.async.wait_group 0;");
    }
    __syncthreads();

    // Phase 1: of[q][t] = vb[q][n]·Wv[:,t] + rb[q][n]·Wrv[:,t]   (i in [i0,i0+32))
    {
        float acc[8];
        #pragma unroll
        for (int q = 0; q < 8; ++q) acc[q] = 0.f;
        #pragma unroll 4
        for (int ii = 0; ii < 32; ++ii) {
            int i = i0 + ii;
            float wv = Wv [i * H + t];
            float wr = Wrv[i * H + t];
            int off = (n * 128 + i) * 4;
            float4 vlo = *(const float4*)&svb[off];
            float4 vhi = *(const float4*)&svb[4096 + off];
            float4 rlo = *(const float4*)&srb[off];
            float4 rhi = *(const float4*)&srb[4096 + off];
            acc[0] += vlo.x * wv + rlo.x * wr;
            acc[1] += vlo.y * wv + rlo.y * wr;
            acc[2] += vlo.z * wv + rlo.z * wr;
            acc[3] += vlo.w * wv + rlo.w * wr;
            acc[4] += vhi.x * wv + rhi.x * wr;
            acc[5] += vhi.y * wv + rhi.y * wr;
            acc[6] += vhi.z * wv + rhi.z * wr;
            acc[7] += vhi.w * wv + rhi.w * wr;
        }
        #pragma unroll
        for (int q = 0; q < 8; ++q) part[g * 1024 + q * 128 + t] = acc[q];
    }
    __syncthreads();
    if (g == 0) {
        float4 lo, hi;
        lo.x = part[0*128+t] + part[1024+0*128+t] + part[2048+0*128+t] + part[3072+0*128+t];
        lo.y = part[1*128+t] + part[1024+1*128+t] + part[2048+1*128+t] + part[3072+1*128+t];
        lo.z = part[2*128+t] + part[1024+2*128+t] + part[2048+2*128+t] + part[3072+2*128+t];
        lo.w = part[3*128+t] + part[1024+3*128+t] + part[2048+3*128+t] + part[3072+3*128+t];
        hi.x = part[4*128+t] + part[1024+4*128+t] + part[2048+4*128+t] + part[3072+4*128+t];
        hi.y = part[5*128+t] + part[1024+5*128+t] + part[2048+5*128+t] + part[3072+5*128+t];
        hi.z = part[6*128+t] + part[1024+6*128+t] + part[2048+6*128+t] + part[3072+6*128+t];
        hi.w = part[7*128+t] + part[1024+7*128+t] + part[2048+7*128+t] + part[3072+7*128+t];
        *(float4*)&sof8[t * 8]     = lo;
        *(float4*)&sof8[t * 8 + 4] = hi;
    }
    __syncthreads();

    // Phase 2: x_out = x + of @ Wo   (i in [i0,i0+32))
    {
        float acc[8];
        #pragma unroll
        for (int q = 0; q < 8; ++q) acc[q] = 0.f;
        #pragma unroll 4
        for (int ii = 0; ii < 32; ++ii) {
            int i = i0 + ii;
            float wo = Wo[i * H + t];
            float4 flo = *(const float4*)&sof8[i * 8];
            float4 fhi = *(const float4*)&sof8[i * 8 + 4];
            acc[0] += flo.x * wo;  acc[1] += flo.y * wo;
            acc[2] += flo.z * wo;  acc[3] += flo.w * wo;
            acc[4] += fhi.x * wo;  acc[5] += fhi.y * wo;
            acc[6] += fhi.z * wo;  acc[7] += fhi.w * wo;
        }
        #pragma unroll
        for (int q = 0; q < 8; ++q) part[g * 1024 + q * 128 + t] = acc[q];
    }
    __syncthreads();
    {
        #pragma unroll
        for (int qq = 0; qq < 2; ++qq) {
            int q = 2 * g + qq;
            float v = xin[(q0 + q) * H + t]
                    + part[q * 128 + t] + part[1024 + q * 128 + t]
                    + part[2048 + q * 128 + t] + part[3072 + q * 128 + t];
            sxo8[q * 128 + t] = v;
            xout[(q0 + q) * H + t] = v;
        }
    }
    __syncthreads();

    if (!do_next) return;

    // Phase 3: next-stage qh = x_out @ Wq2  (group g does queries 2g, 2g+1)
    {
        float a0 = 0.f, a1 = 0.f;
        const float* x0 = &sxo8[(2 * g    ) * 128];
        const float* x1 = &sxo8[(2 * g + 1) * 128];
        #pragma unroll 8
        for (int i = 0; i < H; ++i) {
            float wv = Wq2[i * H + t];
            a0 += x0[i] * wv; a1 += x1[i] * wv;
        }
        part[(2 * g    ) * 128 + t] = a0;
        part[(2 * g + 1) * 128 + t] = a1;
    }
    __syncthreads();

    // Phase 4: u/w; group g handles heads 2g, 2g+1 for all 8 queries.
    #pragma unroll 1
    for (int nn = 0; nn < 2; ++nn) {
        int hn = 2 * g + nn;
        float wk[16], wr[16];
        #pragma unroll
        for (int d = 0; d < 16; ++d) {
            wk[d] = WkT2 [(hn * 16 + d) * H + t];
            wr[d] = WrkT2[(hn * 16 + d) * H + t];
        }
        float uo[8], wo8[8];
        #pragma unroll
        for (int q = 0; q < 8; ++q) { uo[q] = 0.f; wo8[q] = 0.f; }
        #pragma unroll
        for (int d = 0; d < 16; ++d) {
            #pragma unroll
            for (int q = 0; q < 8; ++q) {
                float qv = part[q * 128 + hn * 16 + d];
                uo[q]  += qv * wk[d];
                wo8[q] += qv * wr[d];
            }
        }
        #pragma unroll
        for (int q = 0; q < 8; ++q) {
            gu[(q0 + q) * 1024 + hn * H + t] = uo[q];
            gw[(q0 + q) * 1024 + hn * H + t] = wo8[q];
        }
    }
}

extern "C" void kernel_launch(void* const* d_in, const int* in_sizes, int n_in,
                              void* d_out, int out_size)
{
    bool sig = (in_sizes[6] == 32768);

    const float* x_m    = (const float*)d_in[0];
    const float* x_a    = (const float*)d_in[1];
    const float* x_pl   = (const float*)d_in[2];
    const float* rpe_t  = (const float*)d_in[3];
    const float* rpe_pl = (const float*)d_in[4];
    const float* rpe_a  = (const float*)d_in[5];

    const float* W[3][6];
    int wb = sig ? 6 : 11;
    for (int s = 0; s < 3; ++s)
        for (int j = 0; j < 6; ++j)
            W[s][j] = (const float*)d_in[wb + s * 6 + j];

    int kb = sig ? 24 : 6;
    const int* knn_pl = (const int*)d_in[kb + 0];
    const int* knn_a  = (const int*)d_in[kb + 1];
    const unsigned char* mk_t  = (const unsigned char*)d_in[kb + 2];
    const unsigned char* mk_pl = (const unsigned char*)d_in[kb + 3];
    const unsigned char* mk_a  = (const unsigned char*)d_in[kb + 4];

    cudaFuncSetAttribute(attn_core, cudaFuncAttributeMaxDynamicSharedMemorySize, 65088);
    cudaFuncSetAttribute(out_proj_uw, cudaFuncAttributeMaxDynamicSharedMemorySize, 92160);

    float *buf0, *buf1, *wt, *gu, *gw, *gvb, *grb;
    cudaGetSymbolAddress((void**)&buf0, g_buf0);
    cudaGetSymbolAddress((void**)&buf1, g_buf1);
    cudaGetSymbolAddress((void**)&wt,   g_WT);
    cudaGetSymbolAddress((void**)&gu,   g_u);
    cudaGetSymbolAddress((void**)&gw,   g_w);
    cudaGetSymbolAddress((void**)&gvb,  g_vb);
    cudaGetSymbolAddress((void**)&grb,  g_rb);

    transpose_k<<<48, 128>>>(W[0][1], W[0][3], W[1][1], W[1][3], W[2][1], W[2][3]);

    const int Ss[3] = {50, 32, 16};
    const int Bs[3] = {6, 5, 4};
    const float* cur = x_m;
    float* bufs[2] = {buf0, buf1};
    int bi = 0;

    // First-stage u/w.
    stage_uw<<<NQ / 4, 256>>>(x_m, W[0][0],
                              wt + ((0 * 2 + 0) * 2 + 0) * H * H,
                              wt + ((0 * 2 + 1) * 2 + 0) * H * H, gu, gw);

    for (int idx = 0; idx < 6; ++idx) {
        int l = idx / 3, s = idx % 3;
        int l2 = (idx + 1) / 3, s2 = (idx + 1) % 3;
        float* outp = (idx == 5) ? (float*)d_out : bufs[bi];
        int S = Ss[s], B = Bs[s];
        const float* ksrc = (s == 1) ? x_pl : x_a;
        const float* rp   = (s == 0) ? rpe_t : (s == 1) ? rpe_pl : rpe_a;
        const int*   kn   = (s == 1) ? knn_pl : (s == 2) ? knn_a : (const int*)0;
        const unsigned char* mk = (s == 0) ? mk_t : (s == 1) ? mk_pl : mk_a;

        const float* Wv  = W[s][2] + l * H * H;
        const float* Wrv = W[s][4] + l * H * H;
        const float* Wo  = W[s][5] + l * H * H;

        int P = 128 >> B;
        size_t smemB = (size_t)(2048 + P * 512 + S * 264) * sizeof(float);
        attn_core<<<NQ, 128, smemB>>>(gu, gw, ksrc, rp, kn, mk,
                                      gvb, grb, s + 1, S, B);

        int do_next = (idx < 5);
        const float* Wq2   = do_next ? W[s2][0] + l2 * H * H : Wv;
        const float* WkT2  = do_next ? wt + ((s2 * 2 + 0) * 2 + l2) * H * H : Wv;
        const float* WrkT2 = do_next ? wt + ((s2 * 2 + 1) * 2 + l2) * H * H : Wv;

        out_proj_uw<<<NQ / 8, 512, 90112>>>(cur, gvb, grb, Wv, Wrv, Wo, outp,
                                            Wq2, WkT2, WrkT2, gu, gw, do_next);
        cur = outp;
        bi ^= 1;
    }
}